// round 1
// baseline (speedup 1.0000x reference)
#include <cuda_runtime.h>
#include <math.h>

// ---------------------------------------------------------------------------
// Bit-exact closed-form simulation of:  y=0; repeat steps: y = rn(y + a)
// for IEEE-754 binary32 / binary64 round-to-nearest-even.
//
// Within a binade, the rounded increment (in ulp units) is constant, so we
// jump whole binades with exact integer mantissa arithmetic and only perform
// a real FP add at binade crossings / irregular tie steps (<=1 per binade).
// ---------------------------------------------------------------------------

__device__ __forceinline__ float accum_serial_f32(float eps_in, long long steps) {
    if (steps <= 0) return 0.0f;
    if (eps_in == 0.0f || !isfinite(eps_in)) {
        // degenerate: 0 + 0 ... = 0 ; inf/nan propagate after first add
        return eps_in == 0.0f ? 0.0f : eps_in;
    }
    float a = fabsf(eps_in);
    float sign = (eps_in < 0.0f) ? -1.0f : 1.0f;

    float y = a;          // rn(0 + a) = a exactly
    steps -= 1;

    // decompose addend (fixed for whole run); subnormal: implicit bit 0, e=-126
    unsigned int eb = __float_as_uint(a);
    int eeb = (int)((eb >> 23) & 0xFFu);
    long long me = (long long)(eb & 0x7FFFFFu) | (eeb ? 0x800000LL : 0LL);
    int ee = (eeb ? eeb : 1) - 127;

    while (steps > 0) {
        unsigned int yb = __float_as_uint(y);
        int ybe = (int)((yb >> 23) & 0xFFu);
        if (ybe == 0 || ybe == 255) {        // subnormal y or inf: step manually
            float y2 = y + a;
            if (y2 == y) break;
            y = y2; --steps; continue;
        }
        int e = ybe - 127;
        long long m = (long long)(yb & 0x7FFFFFu) | 0x800000LL;
        int s = e - ee;                       // >= 0 once y >= a (always here)
        long long step;
        if (s <= 0) {
            step = me << (-s);                // addend is exact multiple of ulp
        } else if (s >= 26) {
            step = 0;                         // a < ulp/2 -> saturated
        } else {
            long long q    = me >> s;
            long long rem  = me & ((1LL << s) - 1);
            long long half = 1LL << (s - 1);
            if      (rem < half) step = q;
            else if (rem > half) step = q + 1;
            else {                            // exact tie: round-to-even
                if (m & 1LL) {                // one irregular step, then stable
                    float y2 = y + a;
                    if (y2 == y) break;
                    y = y2; --steps; continue;
                }
                step = (q & 1LL) ? q + 1 : q; // parity-invariant constant step
            }
        }
        if (step <= 0) break;                 // y + a rounds to y forever
        long long room = ((1LL << 24) - 1) - m;  // keep m + n*step < 2^24
        long long n = room / step;
        if (n > steps) n = steps;
        if (n <= 0) {                         // binade-crossing step: do it in FP
            float y2 = y + a;
            if (y2 == y) break;
            y = y2; --steps; continue;
        }
        m += n * step;                        // exact (result < 2^24)
        steps -= n;
        y = ldexpf((float)m, e - 23);         // exact reconstruction
    }
    return sign * y;
}

__device__ __forceinline__ double accum_serial_f64(double a_in, long long steps) {
    if (steps <= 0) return 0.0;
    if (a_in == 0.0 || !isfinite(a_in)) {
        return a_in == 0.0 ? 0.0 : a_in;
    }
    double a = fabs(a_in);
    double sign = (a_in < 0.0) ? -1.0 : 1.0;

    double y = a;
    steps -= 1;

    unsigned long long eb = __double_as_longlong(a);
    int eeb = (int)((eb >> 52) & 0x7FFull);
    long long me = (long long)(eb & 0xFFFFFFFFFFFFFull) |
                   (eeb ? (1LL << 52) : 0LL);
    int ee = (eeb ? eeb : 1) - 1023;

    while (steps > 0) {
        unsigned long long yb = __double_as_longlong(y);
        int ybe = (int)((yb >> 52) & 0x7FFull);
        if (ybe == 0 || ybe == 2047) {
            double y2 = y + a;
            if (y2 == y) break;
            y = y2; --steps; continue;
        }
        int e = ybe - 1023;
        long long m = (long long)(yb & 0xFFFFFFFFFFFFFull) | (1LL << 52);
        int s = e - ee;
        long long step;
        if (s <= 0) {
            step = me << (-s);
        } else if (s >= 55) {
            step = 0;
        } else {
            long long q    = me >> s;
            long long rem  = me & ((1LL << s) - 1);
            long long half = 1LL << (s - 1);
            if      (rem < half) step = q;
            else if (rem > half) step = q + 1;
            else {
                if (m & 1LL) {
                    double y2 = y + a;
                    if (y2 == y) break;
                    y = y2; --steps; continue;
                }
                step = (q & 1LL) ? q + 1 : q;
            }
        }
        if (step <= 0) break;
        long long room = ((1LL << 53) - 1) - m;
        long long n = room / step;
        if (n > steps) n = steps;
        if (n <= 0) {
            double y2 = y + a;
            if (y2 == y) break;
            y = y2; --steps; continue;
        }
        m += n * step;
        steps -= n;
        y = ldexp((double)m, e - 52);          // exact: m < 2^53
    }
    return sign * y;
}

// ---------------------------------------------------------------------------

__global__ void MyModel_61933428409691_kernel(const float* __restrict__ eps_ptr,
                                              float* __restrict__ out,
                                              int out_size) {
    const long long STEPS = 1000000LL;

    // y-path: sequential float32 accumulation of the eps INPUT
    float eps = eps_ptr[0];
    float y = accum_serial_f32(eps, STEPS);

    // x-path: python-double accumulation of the LITERAL 0.001 (reference uses
    // EPS_VAL, not eps.item()), then cast to float32
    double acc = accum_serial_f64(0.001, STEPS);
    float x = (float)acc;

    float r = fabsf(x - y);
    for (int i = 0; i < out_size; ++i) out[i] = r;
}

extern "C" void kernel_launch(void* const* d_in, const int* in_sizes, int n_in,
                              void* d_out, int out_size) {
    // d_in[0] = x (1024*1024 f32, ignored by the reference), d_in[1] = eps (1 f32)
    const float* eps = (const float*)d_in[n_in > 1 ? 1 : 0];
    float* out = (float*)d_out;
    MyModel_61933428409691_kernel<<<1, 1>>>(eps, out, out_size);
}